// round 8
// baseline (speedup 1.0000x reference)
#include <cuda_runtime.h>
#include <cuda_fp16.h>
#include <cstdint>

#define DINLINE __device__ __forceinline__

// ---------------- device scratch (no dynamic alloc allowed) ----------------
static __device__ __align__(16) __half g_xh[8192 * 1024];
static __device__ __align__(16) __half g_fh[3072 * 1024];

// ---------------- portable PTX helpers (sm_80-class ISA only) ----------------
DINLINE uint32_t smem_u32(const void* p) {
    uint32_t a;
    asm("{ .reg .u64 t; cvta.to.shared.u64 t, %1; cvt.u32.u64 %0, t; }" : "=r"(a) : "l"(p));
    return a;
}
DINLINE void cp_async16(uint32_t dst, const void* src) {
    asm volatile("cp.async.cg.shared.global [%0], [%1], 16;" :: "r"(dst), "l"(src) : "memory");
}
DINLINE void cp_commit() { asm volatile("cp.async.commit_group;" ::: "memory"); }
DINLINE void cp_wait0() { asm volatile("cp.async.wait_group 0;" ::: "memory"); }
DINLINE void cp_wait1() { asm volatile("cp.async.wait_group 1;" ::: "memory"); }

DINLINE void ldsm4(uint32_t* r, uint32_t addr) {
    asm volatile("ldmatrix.sync.aligned.m8n8.x4.shared.b16 {%0,%1,%2,%3}, [%4];"
                 : "=r"(r[0]), "=r"(r[1]), "=r"(r[2]), "=r"(r[3]) : "r"(addr));
}
DINLINE void mma_f16(float* c, const uint32_t* a, const uint32_t* b) {
    asm volatile(
        "mma.sync.aligned.m16n8k16.row.col.f32.f16.f16.f32 "
        "{%0,%1,%2,%3}, {%4,%5,%6,%7}, {%8,%9}, {%0,%1,%2,%3};"
        : "+f"(c[0]), "+f"(c[1]), "+f"(c[2]), "+f"(c[3])
        : "r"(a[0]), "r"(a[1]), "r"(a[2]), "r"(a[3]), "r"(b[0]), "r"(b[1]));
}

DINLINE uint32_t pack_h2(__half a, __half b) {
    __half2 t = __halves2half2(a, b);
    return *reinterpret_cast<uint32_t*>(&t);
}

// ==================== kernel 1: convert x -> fp16 ====================
__global__ void __launch_bounds__(256) cvt_x_kernel(const float4* __restrict__ x4) {
    int i = blockIdx.x * 256 + threadIdx.x;   // 2,097,152 float4s total
    float4 v = x4[i];
    reinterpret_cast<uint2*>(g_xh)[i] =
        make_uint2(pack_h2(__float2half(v.x), __float2half(v.y)),
                   pack_h2(__float2half(v.z), __float2half(v.w)));
}

// ==================== kernel 2: rotate W -> filt, store fp16 ====================
// filt[o, r*128+j] = sum_i W[o, r*128+i] * R_sel[r, i, j]
__global__ void __launch_bounds__(256) rotate_kernel(
    const float* __restrict__ W, const float* __restrict__ qR,
    const float* __restrict__ kR, const float* __restrict__ vR) {
    __shared__ float sW[64][128];
    int o0 = blockIdx.x * 64;          // 48 o-tiles
    int r  = blockIdx.y;               // 8 blocks
    int tx = threadIdx.x;              // j: 0..127
    int ty = threadIdx.y;              // 0..1
    int tid = ty * 128 + tx;

    for (int idx = tid; idx < 64 * 128; idx += 256) {
        int row = idx >> 7, i = idx & 127;
        sW[row][i] = W[(size_t)(o0 + row) * 1024 + r * 128 + i];
    }
    __syncthreads();

    const float* R = ((o0 < 1024) ? qR : (o0 < 2048) ? kR : vR) + (size_t)r * 16384;

    float acc[32];
#pragma unroll
    for (int oo = 0; oo < 32; oo++) acc[oo] = 0.0f;

#pragma unroll 4
    for (int i4 = 0; i4 < 32; i4++) {
        float r0 = R[(i4 * 4 + 0) * 128 + tx];
        float r1 = R[(i4 * 4 + 1) * 128 + tx];
        float r2 = R[(i4 * 4 + 2) * 128 + tx];
        float r3 = R[(i4 * 4 + 3) * 128 + tx];
#pragma unroll
        for (int oo = 0; oo < 32; oo++) {
            float4 w = *reinterpret_cast<const float4*>(&sW[ty * 32 + oo][i4 * 4]);
            acc[oo] = fmaf(w.x, r0, fmaf(w.y, r1, fmaf(w.z, r2, fmaf(w.w, r3, acc[oo]))));
        }
    }

#pragma unroll
    for (int oo = 0; oo < 32; oo++) {
        int o = o0 + ty * 32 + oo;
        g_fh[(size_t)o * 1024 + r * 128 + tx] = __float2half(acc[oo]);
    }
}

// ==================== kernel 3: HMMA GEMM, single-term fp16 ====================
// out[8192,3072] = Xh*Fh^T + bias
//
// BM=128, BN=256, BK=64, 3-stage cp.async pipeline, 1 CTA/SM.
// Warp layout 2(M) x 4(N); warp tile 64x64 -> 32 mma : 8 ldsm per k16.
// Fragments double-buffered ACROSS k16 steps: ldsm for kk+1 issues under
// kk's 32-mma chain, hiding LDS latency inside a single warp.
// smem per stage: A 128x128B = 16KB, B 256x128B = 32KB -> 48KB; 3 stages = 144KB.
// XOR swizzle on 128B rows: 16B-chunk c' = c ^ (row & 7).
static constexpr int BM = 128, BN = 256, BK = 64;
static constexpr int NCHUNKS = 1024 / BK;       // 16
static constexpr int STAGE_BYTES = 49152;       // 16KB A + 32KB B
static constexpr int SMEM_SIZE = 3 * STAGE_BYTES;   // 147456 B

DINLINE uint32_t swz(int row, int chunk) {            // byte offset within one array
    return (uint32_t)(row * 128 + (chunk ^ (row & 7)) * 16);
}

DINLINE void load_stage(uint32_t sbase, int m0, int n0, int k0, int tid) {
    // A: 128 rows x 8 chunks = 1024; B: 256 x 8 = 2048. 3072 / 256 thr = 12 each.
#pragma unroll
    for (int t = 0; t < 12; t++) {
        int idx = tid + t * 256;
        if (idx < 1024) {
            int row = idx >> 3, chunk = idx & 7;
            cp_async16(sbase + swz(row, chunk),
                       g_xh + (size_t)(m0 + row) * 1024 + k0 + chunk * 8);
        } else {
            int r2 = idx - 1024;
            int row = r2 >> 3, chunk = r2 & 7;
            cp_async16(sbase + 16384 + swz(row, chunk),
                       g_fh + (size_t)(n0 + row) * 1024 + k0 + chunk * 8);
        }
    }
}

__global__ void __launch_bounds__(256, 1) gemm_kernel(
    const float* __restrict__ bias, float* __restrict__ out) {
    extern __shared__ __align__(128) char smem[];
    uint32_t sm0 = smem_u32(smem);

    int tid = threadIdx.x;
    int wid = tid >> 5, lane = tid & 31;
    int warp_m = wid & 1;                 // 2 warps in M
    int warp_n = wid >> 1;                // 4 warps in N
    int wm = warp_m * 64;                 // warp tile 64 x 64
    int wn = warp_n * 64;
    int m0 = blockIdx.x * BM;
    int n0 = blockIdx.y * BN;

    // per-lane ldmatrix row/half decomposition (validated mapping)
    int a_r    = lane & 15;               // A rows; lanes 16-31 -> k8 half 1
    int a_half = lane >> 4;
    int b_r    = ((lane >> 4) << 3) | (lane & 7);  // B: n-row
    int b_half = (lane >> 3) & 1;                  // k half

    float acc[4][8][4];
#pragma unroll
    for (int i = 0; i < 4; i++)
#pragma unroll
        for (int j = 0; j < 8; j++)
#pragma unroll
            for (int q = 0; q < 4; q++) acc[i][j][q] = 0.0f;

    // prologue: stages 0, 1
    load_stage(sm0, m0, n0, 0, tid); cp_commit();
    load_stage(sm0 + STAGE_BYTES, m0, n0, BK, tid); cp_commit();

    uint32_t af[2][4][4];   // [buf][mt][frag]
    uint32_t bf[2][4][4];   // [buf][n16][frag]

    for (int s = 0; s < NCHUNKS; s++) {
        if (s < NCHUNKS - 1) cp_wait1(); else cp_wait0();
        __syncthreads();

        uint32_t sb = sm0 + (s % 3) * STAGE_BYTES;
        uint32_t sA = sb, sB = sb + 16384;

        // ldsm for k16-step 0 of this stage
#pragma unroll
        for (int mt = 0; mt < 4; mt++)
            ldsm4(af[0][mt], sA + swz(wm + mt * 16 + a_r, a_half));
#pragma unroll
        for (int nt = 0; nt < 4; nt++)
            ldsm4(bf[0][nt], sB + swz(wn + nt * 16 + b_r, b_half));

        // prefetch stage s+2 (after the critical-path ldsm have been issued)
        if (s + 2 < NCHUNKS) {
            load_stage(sm0 + ((s + 2) % 3) * STAGE_BYTES, m0, n0, (s + 2) * BK, tid);
            cp_commit();
        }

#pragma unroll
        for (int kk = 0; kk < 4; kk++) {       // four k16 steps per 64-chunk
            int cur = kk & 1, nxt = cur ^ 1;
            if (kk < 3) {                       // ldsm for kk+1 under kk's mma chain
                int kb = (kk + 1) * 2;
#pragma unroll
                for (int mt = 0; mt < 4; mt++)
                    ldsm4(af[nxt][mt], sA + swz(wm + mt * 16 + a_r, kb + a_half));
#pragma unroll
                for (int nt = 0; nt < 4; nt++)
                    ldsm4(bf[nxt][nt], sB + swz(wn + nt * 16 + b_r, kb + b_half));
            }
#pragma unroll
            for (int mt = 0; mt < 4; mt++)
#pragma unroll
                for (int n8 = 0; n8 < 8; n8++)
                    mma_f16(acc[mt][n8], af[cur][mt], &bf[cur][n8 >> 1][(n8 & 1) * 2]);
        }
    }

    // epilogue: C frag lane mapping: rows l/4, l/4+8; cols (l%4)*2, +1
    int cr = lane >> 2, cc = (lane & 3) * 2;
#pragma unroll
    for (int mt = 0; mt < 4; mt++) {
#pragma unroll
        for (int n8 = 0; n8 < 8; n8++) {
            int col = n0 + wn + n8 * 8 + cc;
            float b0 = __ldg(bias + col), b1 = __ldg(bias + col + 1);
            int row0 = m0 + wm + mt * 16 + cr;
            float2 v0 = make_float2(acc[mt][n8][0] + b0, acc[mt][n8][1] + b1);
            float2 v1 = make_float2(acc[mt][n8][2] + b0, acc[mt][n8][3] + b1);
            *reinterpret_cast<float2*>(out + (size_t)row0 * 3072 + col) = v0;
            *reinterpret_cast<float2*>(out + (size_t)(row0 + 8) * 3072 + col) = v1;
        }
    }
}

// ==================== host ====================
extern "C" void kernel_launch(void* const* d_in, const int* in_sizes, int n_in,
                              void* d_out, int out_size) {
    const float* attn = (const float*)d_in[0];   // [3072, 1024]
    const float* bias = (const float*)d_in[1];   // [3072]
    const float* x    = (const float*)d_in[2];   // [4, 2048, 1024]
    const float* qR   = (const float*)d_in[3];   // [8, 128, 128]
    const float* kR   = (const float*)d_in[4];
    const float* vR   = (const float*)d_in[5];
    float* out = (float*)d_out;                  // [8192, 3072]

    cvt_x_kernel<<<8192, 256>>>(reinterpret_cast<const float4*>(x));
    rotate_kernel<<<dim3(48, 8), dim3(128, 2)>>>(attn, qR, kR, vR);

    cudaFuncSetAttribute(gemm_kernel, cudaFuncAttributeMaxDynamicSharedMemorySize, SMEM_SIZE);
    gemm_kernel<<<dim3(64, 12), 256, SMEM_SIZE>>>(bias, out);
}

// round 9
// speedup vs baseline: 1.1188x; 1.1188x over previous
#include <cuda_runtime.h>
#include <cuda_fp16.h>
#include <cstdint>

#define DINLINE __device__ __forceinline__

// ---------------- device scratch (no dynamic alloc allowed) ----------------
static __device__ __align__(16) __half g_xh[8192 * 1024];
static __device__ __align__(16) __half g_fh[3072 * 1024];

// ---------------- portable PTX helpers (sm_80-class ISA only) ----------------
DINLINE uint32_t smem_u32(const void* p) {
    uint32_t a;
    asm("{ .reg .u64 t; cvta.to.shared.u64 t, %1; cvt.u32.u64 %0, t; }" : "=r"(a) : "l"(p));
    return a;
}
DINLINE void cp_async16(uint32_t dst, const void* src) {
    asm volatile("cp.async.cg.shared.global [%0], [%1], 16;" :: "r"(dst), "l"(src) : "memory");
}
DINLINE void cp_commit() { asm volatile("cp.async.commit_group;" ::: "memory"); }
DINLINE void cp_wait0() { asm volatile("cp.async.wait_group 0;" ::: "memory"); }
DINLINE void cp_wait1() { asm volatile("cp.async.wait_group 1;" ::: "memory"); }

DINLINE void ldsm4(uint32_t* r, uint32_t addr) {
    asm volatile("ldmatrix.sync.aligned.m8n8.x4.shared.b16 {%0,%1,%2,%3}, [%4];"
                 : "=r"(r[0]), "=r"(r[1]), "=r"(r[2]), "=r"(r[3]) : "r"(addr));
}
DINLINE void mma_f16(float* c, const uint32_t* a, const uint32_t* b) {
    asm volatile(
        "mma.sync.aligned.m16n8k16.row.col.f32.f16.f16.f32 "
        "{%0,%1,%2,%3}, {%4,%5,%6,%7}, {%8,%9}, {%0,%1,%2,%3};"
        : "+f"(c[0]), "+f"(c[1]), "+f"(c[2]), "+f"(c[3])
        : "r"(a[0]), "r"(a[1]), "r"(a[2]), "r"(a[3]), "r"(b[0]), "r"(b[1]));
}

DINLINE uint32_t pack_h2(__half a, __half b) {
    __half2 t = __halves2half2(a, b);
    return *reinterpret_cast<uint32_t*>(&t);
}

// ==================== kernel 1: convert x -> fp16 ====================
__global__ void __launch_bounds__(256) cvt_x_kernel(const float4* __restrict__ x4) {
    int i = blockIdx.x * 256 + threadIdx.x;   // 2,097,152 float4s total
    float4 v = x4[i];
    reinterpret_cast<uint2*>(g_xh)[i] =
        make_uint2(pack_h2(__float2half(v.x), __float2half(v.y)),
                   pack_h2(__float2half(v.z), __float2half(v.w)));
}

// ==================== kernel 2: rotate W -> filt, store fp16 ====================
// filt[o, r*128+j] = sum_i W[o, r*128+i] * R_sel[r, i, j]
__global__ void __launch_bounds__(256) rotate_kernel(
    const float* __restrict__ W, const float* __restrict__ qR,
    const float* __restrict__ kR, const float* __restrict__ vR) {
    __shared__ float sW[64][128];
    int o0 = blockIdx.x * 64;          // 48 o-tiles
    int r  = blockIdx.y;               // 8 blocks
    int tx = threadIdx.x;              // j: 0..127
    int ty = threadIdx.y;              // 0..1
    int tid = ty * 128 + tx;

    for (int idx = tid; idx < 64 * 128; idx += 256) {
        int row = idx >> 7, i = idx & 127;
        sW[row][i] = W[(size_t)(o0 + row) * 1024 + r * 128 + i];
    }
    __syncthreads();

    const float* R = ((o0 < 1024) ? qR : (o0 < 2048) ? kR : vR) + (size_t)r * 16384;

    float acc[32];
#pragma unroll
    for (int oo = 0; oo < 32; oo++) acc[oo] = 0.0f;

#pragma unroll 4
    for (int i4 = 0; i4 < 32; i4++) {
        float r0 = R[(i4 * 4 + 0) * 128 + tx];
        float r1 = R[(i4 * 4 + 1) * 128 + tx];
        float r2 = R[(i4 * 4 + 2) * 128 + tx];
        float r3 = R[(i4 * 4 + 3) * 128 + tx];
#pragma unroll
        for (int oo = 0; oo < 32; oo++) {
            float4 w = *reinterpret_cast<const float4*>(&sW[ty * 32 + oo][i4 * 4]);
            acc[oo] = fmaf(w.x, r0, fmaf(w.y, r1, fmaf(w.z, r2, fmaf(w.w, r3, acc[oo]))));
        }
    }

#pragma unroll
    for (int oo = 0; oo < 32; oo++) {
        int o = o0 + ty * 32 + oo;
        g_fh[(size_t)o * 1024 + r * 128 + tx] = __float2half(acc[oo]);
    }
}

// ==================== kernel 3: HMMA GEMM, single-term fp16 ====================
// out[8192,3072] = Xh*Fh^T + bias
//
// BM=128, BN=128, BK=64, 3-stage cp.async pipeline, 2 CTAs/SM (4 warps/SMSP).
// Warp layout 2(M) x 4(N); warp tile 64x32.
// Stage flattened to a 16-iteration (kk,mt) software pipeline:
//   A frag for iter i+1 ldsm'd under iter i's 4-mma chain,
//   B frags for kk+1 ldsm'd under kk's mt=0 / mt=1 iterations.
// Only the post-__syncthreads boundary fill (1 A + 2 B ldsm) stays exposed.
// smem per stage: A, B each 128 rows x 128B (swizzled) = 32KB; 3 stages = 96KB.
// XOR swizzle on 128B rows: 16B-chunk c' = c ^ (row & 7).
static constexpr int BM = 128, BN = 128, BK = 64;
static constexpr int NCHUNKS = 1024 / BK;       // 16
static constexpr int STAGE_BYTES = 32768;
static constexpr int SMEM_SIZE = 3 * STAGE_BYTES;   // 96KB -> 2 CTAs/SM (192KB)

DINLINE uint32_t swz(int row, int chunk) {            // byte offset within one 16KB array
    return (uint32_t)(row * 128 + (chunk ^ (row & 7)) * 16);
}

DINLINE void load_stage(uint32_t sbase, int m0, int n0, int k0, int tid) {
    // 2 arrays x 128 rows x 8 chunks = 2048 cp.async / 256 threads = 8 each
#pragma unroll
    for (int t = 0; t < 8; t++) {
        int idx = tid + t * 256;
        int arr = idx >> 10;         // 0:A 1:B
        int rem = idx & 1023;
        int row = rem >> 3, chunk = rem & 7;
        const __half* src = (arr == 0)
            ? g_xh + (size_t)(m0 + row) * 1024 + k0 + chunk * 8
            : g_fh + (size_t)(n0 + row) * 1024 + k0 + chunk * 8;
        cp_async16(sbase + arr * 16384 + swz(row, chunk), src);
    }
}

__global__ void __launch_bounds__(256, 2) gemm_kernel(
    const float* __restrict__ bias, float* __restrict__ out) {
    extern __shared__ __align__(128) char smem[];
    uint32_t sm0 = smem_u32(smem);

    int tid = threadIdx.x;
    int wid = tid >> 5, lane = tid & 31;
    int warp_m = wid & 1;                 // 2 warps in M
    int warp_n = wid >> 1;                // 4 warps in N
    int wm = warp_m * 64;                 // warp tile 64 x 32
    int wn = warp_n * 32;
    int m0 = blockIdx.x * BM;
    int n0 = blockIdx.y * BN;

    // per-lane ldmatrix row/half decomposition (validated mapping)
    int a_r    = lane & 15;               // A rows; lanes 16-31 -> k8 half 1
    int a_half = lane >> 4;
    int b_r    = ((lane >> 4) << 3) | (lane & 7);  // B: n-row
    int b_half = (lane >> 3) & 1;                  // k half

    float acc[4][4][4];
#pragma unroll
    for (int i = 0; i < 4; i++)
#pragma unroll
        for (int j = 0; j < 4; j++)
#pragma unroll
            for (int q = 0; q < 4; q++) acc[i][j][q] = 0.0f;

    // prologue: stages 0, 1
    load_stage(sm0, m0, n0, 0, tid); cp_commit();
    load_stage(sm0 + STAGE_BYTES, m0, n0, BK, tid); cp_commit();

    uint32_t af[2][4];       // A frag, rolling across (kk,mt) iterations
    uint32_t bf[2][2][4];    // B frags, rolling across kk

    for (int s = 0; s < NCHUNKS; s++) {
        if (s < NCHUNKS - 1) cp_wait1(); else cp_wait0();
        __syncthreads();

        uint32_t sb = sm0 + (s % 3) * STAGE_BYTES;
        uint32_t sA = sb, sB = sb + 16384;

        // boundary fill: B for kk=0 (both n16 tiles) and A for (kk=0, mt=0)
        ldsm4(bf[0][0], sB + swz(wn + b_r, b_half));
        ldsm4(bf[0][1], sB + swz(wn + 16 + b_r, b_half));
        ldsm4(af[0],    sA + swz(wm + a_r, a_half));

        // prefetch stage s+2 after critical-path ldsm have been issued
        if (s + 2 < NCHUNKS) {
            load_stage(sm0 + ((s + 2) % 3) * STAGE_BYTES, m0, n0, (s + 2) * BK, tid);
            cp_commit();
        }

        // 16-iteration pipeline: it = kk*4 + mt
#pragma unroll
        for (int it = 0; it < 16; it++) {
            int kk = it >> 2, mt = it & 3;
            int abuf = it & 1, bbuf = kk & 1;
            if (it < 15) {     // A frag for next iteration
                int it1 = it + 1;
                ldsm4(af[abuf ^ 1],
                      sA + swz(wm + (it1 & 3) * 16 + a_r, (it1 >> 2) * 2 + a_half));
            }
            if (kk < 3) {      // B frags for next k16 step, spread over mt=0,1
                if (mt == 0)
                    ldsm4(bf[bbuf ^ 1][0], sB + swz(wn + b_r, (kk + 1) * 2 + b_half));
                else if (mt == 1)
                    ldsm4(bf[bbuf ^ 1][1], sB + swz(wn + 16 + b_r, (kk + 1) * 2 + b_half));
            }
#pragma unroll
            for (int n8 = 0; n8 < 4; n8++)
                mma_f16(acc[mt][n8], af[abuf], &bf[bbuf][n8 >> 1][(n8 & 1) * 2]);
        }
    }

    // epilogue: C frag lane mapping: rows l/4, l/4+8; cols (l%4)*2, +1
    int cr = lane >> 2, cc = (lane & 3) * 2;
#pragma unroll
    for (int mt = 0; mt < 4; mt++) {
#pragma unroll
        for (int n8 = 0; n8 < 4; n8++) {
            int col = n0 + wn + n8 * 8 + cc;
            float b0 = __ldg(bias + col), b1 = __ldg(bias + col + 1);
            int row0 = m0 + wm + mt * 16 + cr;
            float2 v0 = make_float2(acc[mt][n8][0] + b0, acc[mt][n8][1] + b1);
            float2 v1 = make_float2(acc[mt][n8][2] + b0, acc[mt][n8][3] + b1);
            *reinterpret_cast<float2*>(out + (size_t)row0 * 3072 + col) = v0;
            *reinterpret_cast<float2*>(out + (size_t)(row0 + 8) * 3072 + col) = v1;
        }
    }
}

// ==================== host ====================
extern "C" void kernel_launch(void* const* d_in, const int* in_sizes, int n_in,
                              void* d_out, int out_size) {
    const float* attn = (const float*)d_in[0];   // [3072, 1024]
    const float* bias = (const float*)d_in[1];   // [3072]
    const float* x    = (const float*)d_in[2];   // [4, 2048, 1024]
    const float* qR   = (const float*)d_in[3];   // [8, 128, 128]
    const float* kR   = (const float*)d_in[4];
    const float* vR   = (const float*)d_in[5];
    float* out = (float*)d_out;                  // [8192, 3072]

    cvt_x_kernel<<<8192, 256>>>(reinterpret_cast<const float4*>(x));
    rotate_kernel<<<dim3(48, 8), dim3(128, 2)>>>(attn, qR, kR, vR);

    cudaFuncSetAttribute(gemm_kernel, cudaFuncAttributeMaxDynamicSharedMemorySize, SMEM_SIZE);
    gemm_kernel<<<dim3(64, 24), 256, SMEM_SIZE>>>(bias, out);
}

// round 10
// speedup vs baseline: 1.1237x; 1.0043x over previous
#include <cuda_runtime.h>
#include <cuda_fp16.h>
#include <cstdint>

#define DINLINE __device__ __forceinline__

// ---------------- device scratch (no dynamic alloc allowed) ----------------
static __device__ __align__(16) __half g_xh[8192 * 1024];
static __device__ __align__(16) __half g_fh[3072 * 1024];

// ---------------- portable PTX helpers (sm_80-class ISA only) ----------------
DINLINE uint32_t smem_u32(const void* p) {
    uint32_t a;
    asm("{ .reg .u64 t; cvta.to.shared.u64 t, %1; cvt.u32.u64 %0, t; }" : "=r"(a) : "l"(p));
    return a;
}
DINLINE void cp_async16(uint32_t dst, const void* src) {
    asm volatile("cp.async.cg.shared.global [%0], [%1], 16;" :: "r"(dst), "l"(src) : "memory");
}
DINLINE void cp_commit() { asm volatile("cp.async.commit_group;" ::: "memory"); }
DINLINE void cp_wait0() { asm volatile("cp.async.wait_group 0;" ::: "memory"); }
DINLINE void cp_wait1() { asm volatile("cp.async.wait_group 1;" ::: "memory"); }

DINLINE void ldsm4(uint32_t* r, uint32_t addr) {
    asm volatile("ldmatrix.sync.aligned.m8n8.x4.shared.b16 {%0,%1,%2,%3}, [%4];"
                 : "=r"(r[0]), "=r"(r[1]), "=r"(r[2]), "=r"(r[3]) : "r"(addr));
}
DINLINE void mma_f16(float* c, const uint32_t* a, const uint32_t* b) {
    asm volatile(
        "mma.sync.aligned.m16n8k16.row.col.f32.f16.f16.f32 "
        "{%0,%1,%2,%3}, {%4,%5,%6,%7}, {%8,%9}, {%0,%1,%2,%3};"
        : "+f"(c[0]), "+f"(c[1]), "+f"(c[2]), "+f"(c[3])
        : "r"(a[0]), "r"(a[1]), "r"(a[2]), "r"(a[3]), "r"(b[0]), "r"(b[1]));
}

DINLINE uint32_t pack_h2(__half a, __half b) {
    __half2 t = __halves2half2(a, b);
    return *reinterpret_cast<uint32_t*>(&t);
}

// ==================== kernel 1: convert x -> fp16 ====================
__global__ void __launch_bounds__(256) cvt_x_kernel(const float4* __restrict__ x4) {
    int i = blockIdx.x * 256 + threadIdx.x;   // 2,097,152 float4s total
    float4 v = x4[i];
    reinterpret_cast<uint2*>(g_xh)[i] =
        make_uint2(pack_h2(__float2half(v.x), __float2half(v.y)),
                   pack_h2(__float2half(v.z), __float2half(v.w)));
}

// ==================== kernel 2: rotate W -> filt, store fp16 ====================
// filt[o, r*128+j] = sum_i W[o, r*128+i] * R_sel[r, i, j]
__global__ void __launch_bounds__(256) rotate_kernel(
    const float* __restrict__ W, const float* __restrict__ qR,
    const float* __restrict__ kR, const float* __restrict__ vR) {
    __shared__ float sW[64][128];
    int o0 = blockIdx.x * 64;          // 48 o-tiles
    int r  = blockIdx.y;               // 8 blocks
    int tx = threadIdx.x;              // j: 0..127
    int ty = threadIdx.y;              // 0..1
    int tid = ty * 128 + tx;

    for (int idx = tid; idx < 64 * 128; idx += 256) {
        int row = idx >> 7, i = idx & 127;
        sW[row][i] = W[(size_t)(o0 + row) * 1024 + r * 128 + i];
    }
    __syncthreads();

    const float* R = ((o0 < 1024) ? qR : (o0 < 2048) ? kR : vR) + (size_t)r * 16384;

    float acc[32];
#pragma unroll
    for (int oo = 0; oo < 32; oo++) acc[oo] = 0.0f;

#pragma unroll 4
    for (int i4 = 0; i4 < 32; i4++) {
        float r0 = R[(i4 * 4 + 0) * 128 + tx];
        float r1 = R[(i4 * 4 + 1) * 128 + tx];
        float r2 = R[(i4 * 4 + 2) * 128 + tx];
        float r3 = R[(i4 * 4 + 3) * 128 + tx];
#pragma unroll
        for (int oo = 0; oo < 32; oo++) {
            float4 w = *reinterpret_cast<const float4*>(&sW[ty * 32 + oo][i4 * 4]);
            acc[oo] = fmaf(w.x, r0, fmaf(w.y, r1, fmaf(w.z, r2, fmaf(w.w, r3, acc[oo]))));
        }
    }

#pragma unroll
    for (int oo = 0; oo < 32; oo++) {
        int o = o0 + ty * 32 + oo;
        g_fh[(size_t)o * 1024 + r * 128 + tx] = __float2half(acc[oo]);
    }
}

// ==================== kernel 3: HMMA GEMM, single-term fp16 ====================
// out[8192,3072] = Xh*Fh^T + bias
//
// BM=128, BN=128, BK=64, 3-stage cp.async pipeline, 128 threads (4 warps),
// 2 CTAs/SM. Warp layout 2(M) x 2(N); warp tile 64x64.
// smem reads/MAC halved vs 64x32 tile: per stage per CTA reads = A 16KB*2 +
// B 16KB*2 = 64KB (+32KB writes) -> smem crossbar ~73% vs tensor 100%.
// The two CTAs' barriers are independent, covering each other's stalls.
// XOR swizzle on 128B rows: 16B-chunk c' = c ^ (row & 7).
static constexpr int BM = 128, BN = 128, BK = 64;
static constexpr int NCHUNKS = 1024 / BK;       // 16
static constexpr int STAGE_BYTES = 32768;
static constexpr int SMEM_SIZE = 3 * STAGE_BYTES;   // 96KB -> 2 CTAs/SM (192KB)

DINLINE uint32_t swz(int row, int chunk) {            // byte offset within one 16KB array
    return (uint32_t)(row * 128 + (chunk ^ (row & 7)) * 16);
}

DINLINE void load_stage(uint32_t sbase, int m0, int n0, int k0, int tid) {
    // 2 arrays x 128 rows x 8 chunks = 2048 cp.async / 128 threads = 16 each
#pragma unroll
    for (int t = 0; t < 16; t++) {
        int idx = tid + t * 128;
        int arr = idx >> 10;         // 0:A 1:B
        int rem = idx & 1023;
        int row = rem >> 3, chunk = rem & 7;
        const __half* src = (arr == 0)
            ? g_xh + (size_t)(m0 + row) * 1024 + k0 + chunk * 8
            : g_fh + (size_t)(n0 + row) * 1024 + k0 + chunk * 8;
        cp_async16(sbase + arr * 16384 + swz(row, chunk), src);
    }
}

__global__ void __launch_bounds__(128, 2) gemm_kernel(
    const float* __restrict__ bias, float* __restrict__ out) {
    extern __shared__ __align__(128) char smem[];
    uint32_t sm0 = smem_u32(smem);

    int tid = threadIdx.x;
    int wid = tid >> 5, lane = tid & 31;
    int warp_m = wid & 1;                 // 2 warps in M
    int warp_n = wid >> 1;                // 2 warps in N
    int wm = warp_m * 64;                 // warp tile 64 x 64
    int wn = warp_n * 64;
    int m0 = blockIdx.x * BM;
    int n0 = blockIdx.y * BN;

    // per-lane ldmatrix row/half decomposition (validated mapping)
    int a_r    = lane & 15;               // A rows; lanes 16-31 -> k8 half 1
    int a_half = lane >> 4;
    int b_r    = ((lane >> 4) << 3) | (lane & 7);  // B: n-row
    int b_half = (lane >> 3) & 1;                  // k half

    float acc[4][8][4];
#pragma unroll
    for (int i = 0; i < 4; i++)
#pragma unroll
        for (int j = 0; j < 8; j++)
#pragma unroll
            for (int q = 0; q < 4; q++) acc[i][j][q] = 0.0f;

    // prologue: stages 0, 1
    load_stage(sm0, m0, n0, 0, tid); cp_commit();
    load_stage(sm0 + STAGE_BYTES, m0, n0, BK, tid); cp_commit();

    uint32_t af[2][4][4];   // [buf][mt][frag]
    uint32_t bf[2][4][4];   // [buf][nt][frag]

    for (int s = 0; s < NCHUNKS; s++) {
        if (s < NCHUNKS - 1) cp_wait1(); else cp_wait0();
        __syncthreads();

        uint32_t sb = sm0 + (s % 3) * STAGE_BYTES;
        uint32_t sA = sb, sB = sb + 16384;

        // boundary fill: fragments for k16-step 0 of this stage
#pragma unroll
        for (int mt = 0; mt < 4; mt++)
            ldsm4(af[0][mt], sA + swz(wm + mt * 16 + a_r, a_half));
#pragma unroll
        for (int nt = 0; nt < 4; nt++)
            ldsm4(bf[0][nt], sB + swz(wn + nt * 16 + b_r, b_half));

        // prefetch stage s+2 after critical-path ldsm have been issued
        if (s + 2 < NCHUNKS) {
            load_stage(sm0 + ((s + 2) % 3) * STAGE_BYTES, m0, n0, (s + 2) * BK, tid);
            cp_commit();
        }

#pragma unroll
        for (int kk = 0; kk < 4; kk++) {       // four k16 steps per 64-chunk
            int cur = kk & 1, nxt = cur ^ 1;
            if (kk < 3) {                       // frags for kk+1 under kk's 32-mma chain
                int kb = (kk + 1) * 2;
#pragma unroll
                for (int mt = 0; mt < 4; mt++)
                    ldsm4(af[nxt][mt], sA + swz(wm + mt * 16 + a_r, kb + a_half));
#pragma unroll
                for (int nt = 0; nt < 4; nt++)
                    ldsm4(bf[nxt][nt], sB + swz(wn + nt * 16 + b_r, kb + b_half));
            }
#pragma unroll
            for (int mt = 0; mt < 4; mt++)
#pragma unroll
                for (int n8 = 0; n8 < 8; n8++)
                    mma_f16(acc[mt][n8], af[cur][mt], &bf[cur][n8 >> 1][(n8 & 1) * 2]);
        }
    }

    // epilogue: C frag lane mapping: rows l/4, l/4+8; cols (l%4)*2, +1
    int cr = lane >> 2, cc = (lane & 3) * 2;
#pragma unroll
    for (int mt = 0; mt < 4; mt++) {
#pragma unroll
        for (int n8 = 0; n8 < 8; n8++) {
            int col = n0 + wn + n8 * 8 + cc;
            float b0 = __ldg(bias + col), b1 = __ldg(bias + col + 1);
            int row0 = m0 + wm + mt * 16 + cr;
            float2 v0 = make_float2(acc[mt][n8][0] + b0, acc[mt][n8][1] + b1);
            float2 v1 = make_float2(acc[mt][n8][2] + b0, acc[mt][n8][3] + b1);
            *reinterpret_cast<float2*>(out + (size_t)row0 * 3072 + col) = v0;
            *reinterpret_cast<float2*>(out + (size_t)(row0 + 8) * 3072 + col) = v1;
        }
    }
}

// ==================== host ====================
extern "C" void kernel_launch(void* const* d_in, const int* in_sizes, int n_in,
                              void* d_out, int out_size) {
    const float* attn = (const float*)d_in[0];   // [3072, 1024]
    const float* bias = (const float*)d_in[1];   // [3072]
    const float* x    = (const float*)d_in[2];   // [4, 2048, 1024]
    const float* qR   = (const float*)d_in[3];   // [8, 128, 128]
    const float* kR   = (const float*)d_in[4];
    const float* vR   = (const float*)d_in[5];
    float* out = (float*)d_out;                  // [8192, 3072]

    cvt_x_kernel<<<8192, 256>>>(reinterpret_cast<const float4*>(x));
    rotate_kernel<<<dim3(48, 8), dim3(128, 2)>>>(attn, qR, kR, vR);

    cudaFuncSetAttribute(gemm_kernel, cudaFuncAttributeMaxDynamicSharedMemorySize, SMEM_SIZE);
    gemm_kernel<<<dim3(64, 24), 128, SMEM_SIZE>>>(bias, out);
}